// round 1
// baseline (speedup 1.0000x reference)
#include <cuda_runtime.h>
#include <math.h>

#define B_  8
#define S_  1024
#define D_  1024
#define R_  128
#define NH  16
#define DH  64

// ---------------- scratch (device globals; no allocation) ----------------
__device__ float g_accum[B_ * 128];
__device__ int   g_idx[B_ * 18];
__device__ float g_w[B_ * 18];
__device__ float g_SC [B_ * D_ * R_];          // [B,D,R]
__device__ float g_h  [B_ * S_ * R_];          // [B,S,R]
__device__ float g_eQK[B_ * R_ * D_];          // [B,R,D]
__device__ float g_eV [B_ * R_ * D_];
__device__ float g_Q  [B_ * S_ * D_];          // [B,S,D]
__device__ float g_V  [B_ * S_ * D_];
__device__ float g_AO [B_ * S_ * D_];          // attention output

// ---------------- zero accumulator ----------------
__global__ void zero_accum_kernel() {
    int i = blockIdx.x * 256 + threadIdx.x;
    if (i < B_ * 128) g_accum[i] = 0.f;
}

// ---------------- routing: logits + softmax + importance-weighted reduce ----------------
// Block = 32 tokens of one batch. 512 threads. Outputs atomicAdd into g_accum[b][128].
__global__ __launch_bounds__(512) void routing_kernel(
    const float* __restrict__ x, const float* __restrict__ importance,
    const float* __restrict__ Wc, const float* __restrict__ Wqk,
    const float* __restrict__ Wv)
{
    __shared__ float Xs[32][33];
    __shared__ float Ws[128][33];
    __shared__ float logits[32][130];
    __shared__ float ssum[32][3];
    __shared__ float simp[32];

    int b  = blockIdx.y;
    int t0 = blockIdx.x * 32;
    int tid = threadIdx.x;
    int o = tid & 127;          // output neuron 0..127
    int g = tid >> 7;           // token group 0..3 (8 tokens each)

    float acc[8];
#pragma unroll
    for (int i = 0; i < 8; i++) acc[i] = 0.f;

    const float* xb = x + ((size_t)b * S_ + t0) * D_;

    for (int k0 = 0; k0 < D_; k0 += 32) {
        for (int e = tid; e < 32 * 32; e += 512) {
            int t = e >> 5, k = e & 31;
            Xs[t][k] = xb[t * D_ + k0 + k];
        }
        for (int e = tid; e < 128 * 32; e += 512) {
            int oo = e >> 5, k = e & 31;
            const float* wr = (oo < 64) ? Wc + oo * D_
                            : (oo < 96) ? Wqk + (oo - 64) * D_
                                        : Wv  + (oo - 96) * D_;
            Ws[oo][k] = wr[k0 + k];
        }
        __syncthreads();
#pragma unroll
        for (int kk = 0; kk < 32; kk++) {
            float w = Ws[o][kk];
#pragma unroll
            for (int i = 0; i < 8; i++) acc[i] += Xs[g * 8 + i][kk] * w;
        }
        __syncthreads();
    }
#pragma unroll
    for (int i = 0; i < 8; i++) logits[g * 8 + i][o] = acc[i];
    if (tid < 32) simp[tid] = importance[b * S_ + t0 + tid];
    __syncthreads();

    // per-token softmax over the three segments [0:64), [64:96), [96:128)
    if (tid < 96) {
        int t = tid & 31;
        int seg = tid >> 5;
        int off = (seg == 0) ? 0 : (seg == 1) ? 64 : 96;
        int n   = (seg == 0) ? 64 : 32;
        float mx = -1e30f;
        for (int c = 0; c < n; c++) mx = fmaxf(mx, logits[t][off + c]);
        float sum = 0.f;
        for (int c = 0; c < n; c++) {
            float p = expf(logits[t][off + c] - mx);
            logits[t][off + c] = p;
            sum += p;
        }
        ssum[t][seg] = sum;
    }
    __syncthreads();

    if (tid < 128) {
        int seg = (tid < 64) ? 0 : (tid < 96) ? 1 : 2;
        float a = 0.f;
        for (int t = 0; t < 32; t++)
            a += simp[t] * logits[t][tid] / ssum[t][seg];
        atomicAdd(&g_accum[b * 128 + tid], a);
    }
}

// ---------------- exact top-k sparsify + renormalize ----------------
__global__ void topk_kernel() {
    int b = threadIdx.x;
    if (b >= B_) return;
    const int offs[3]  = {0, 64, 96};
    const int ns[3]    = {64, 32, 32};
    const int ks[3]    = {8, 4, 6};
    const int slots[3] = {0, 8, 12};
    for (int s = 0; s < 3; s++) {
        float vals[64];
        int n = ns[s], k = ks[s];
        for (int i = 0; i < n; i++) vals[i] = g_accum[b * 128 + offs[s] + i];
        float sum = 0.f;
        for (int j = 0; j < k; j++) {
            int am = 0; float mv = vals[0];
            for (int i = 1; i < n; i++) if (vals[i] > mv) { mv = vals[i]; am = i; }
            g_idx[b * 18 + slots[s] + j] = am;
            g_w  [b * 18 + slots[s] + j] = mv;
            sum += mv;
            vals[am] = -1e30f;
        }
        float inv = 1.f / (sum + 1e-8f);
        for (int j = 0; j < k; j++) g_w[b * 18 + slots[s] + j] *= inv;
    }
}

// ---------------- sparse neuron mix: dst[b, e] = sum_j w_j * W[idx_j, e] ----------------
// Each neuron slab is 131072 floats (D*R == R*D).
__global__ void mix_kernel(const float* __restrict__ W, float* __restrict__ dst,
                           int slot, int cnt)
{
    int b = blockIdx.y;
    int e = blockIdx.x * 256 + threadIdx.x;   // 0..131071
    float acc = 0.f;
    for (int j = 0; j < cnt; j++) {
        int   n = g_idx[b * 18 + slot + j];
        float w = g_w [b * 18 + slot + j];
        acc += w * W[(size_t)n * 131072 + e];
    }
    dst[(size_t)b * 131072 + e] = acc;
}

// ---------------- tiled SGEMM: C = A(MxK, row) * B(KxN, row) ----------------
#define BM 64
#define BN 64
#define BK 16
__global__ __launch_bounds__(256) void sgemm_nn(
    const float* __restrict__ A, const float* __restrict__ B, float* __restrict__ C,
    int M, int N, int K, int lda, int ldb, int ldc,
    long sA, long sB, long sC)
{
    __shared__ float As[BK][BM + 1];
    __shared__ float Bs[BK][BN + 1];
    A += (size_t)blockIdx.z * sA;
    B += (size_t)blockIdx.z * sB;
    C += (size_t)blockIdx.z * sC;
    int m0 = blockIdx.y * BM, n0 = blockIdx.x * BN;
    int tid = threadIdx.x;
    int tx = tid & 15, ty = tid >> 4;
    float acc[4][4];
#pragma unroll
    for (int i = 0; i < 4; i++)
#pragma unroll
        for (int j = 0; j < 4; j++) acc[i][j] = 0.f;

    for (int k0 = 0; k0 < K; k0 += BK) {
        for (int e = tid; e < BM * BK; e += 256) {
            int m = e >> 4, k = e & 15;
            As[k][m] = A[(size_t)(m0 + m) * lda + k0 + k];
        }
        for (int e = tid; e < BK * BN; e += 256) {
            int k = e >> 6, n = e & 63;
            Bs[k][n] = B[(size_t)(k0 + k) * ldb + n0 + n];
        }
        __syncthreads();
#pragma unroll
        for (int kk = 0; kk < BK; kk++) {
            float a[4], bb[4];
#pragma unroll
            for (int i = 0; i < 4; i++) a[i]  = As[kk][ty * 4 + i];
#pragma unroll
            for (int j = 0; j < 4; j++) bb[j] = Bs[kk][tx * 4 + j];
#pragma unroll
            for (int i = 0; i < 4; i++)
#pragma unroll
                for (int j = 0; j < 4; j++) acc[i][j] += a[i] * bb[j];
        }
        __syncthreads();
    }
#pragma unroll
    for (int i = 0; i < 4; i++)
#pragma unroll
        for (int j = 0; j < 4; j++)
            C[(size_t)(m0 + ty * 4 + i) * ldc + n0 + tx * 4 + j] = acc[i][j];
}

// ---------------- tiled SGEMM: C = A(MxK, row) * Bt(NxK, row)^T ----------------
__global__ __launch_bounds__(256) void sgemm_bt(
    const float* __restrict__ A, const float* __restrict__ Bt, float* __restrict__ C,
    int M, int N, int K, int lda, int ldb, int ldc)
{
    __shared__ float As[BK][BM + 1];
    __shared__ float Bs[BK][BN + 1];
    int m0 = blockIdx.y * BM, n0 = blockIdx.x * BN;
    int tid = threadIdx.x;
    int tx = tid & 15, ty = tid >> 4;
    float acc[4][4];
#pragma unroll
    for (int i = 0; i < 4; i++)
#pragma unroll
        for (int j = 0; j < 4; j++) acc[i][j] = 0.f;

    for (int k0 = 0; k0 < K; k0 += BK) {
        for (int e = tid; e < BM * BK; e += 256) {
            int m = e >> 4, k = e & 15;
            As[k][m] = A[(size_t)(m0 + m) * lda + k0 + k];
        }
        for (int e = tid; e < BN * BK; e += 256) {
            int n = e >> 4, k = e & 15;
            Bs[k][n] = Bt[(size_t)(n0 + n) * ldb + k0 + k];
        }
        __syncthreads();
#pragma unroll
        for (int kk = 0; kk < BK; kk++) {
            float a[4], bb[4];
#pragma unroll
            for (int i = 0; i < 4; i++) a[i]  = As[kk][ty * 4 + i];
#pragma unroll
            for (int j = 0; j < 4; j++) bb[j] = Bs[kk][tx * 4 + j];
#pragma unroll
            for (int i = 0; i < 4; i++)
#pragma unroll
                for (int j = 0; j < 4; j++) acc[i][j] += a[i] * bb[j];
        }
        __syncthreads();
    }
#pragma unroll
    for (int i = 0; i < 4; i++)
#pragma unroll
        for (int j = 0; j < 4; j++)
            C[(size_t)(m0 + ty * 4 + i) * ldc + n0 + tx * 4 + j] = acc[i][j];
}

// ---------------- flash attention, fp32, K == Q, causal ----------------
// grid (S/64, NH, B), 256 threads, dynamic smem.
#define ASM_F ((4 * 64 * 65 + 3 * 64))
__global__ __launch_bounds__(256) void attn_kernel(
    const float* __restrict__ Q, const float* __restrict__ V, float* __restrict__ O)
{
    extern __shared__ float sm[];
    float* Qs  = sm;                    // [64][65]
    float* Ks  = Qs + 64 * 65;
    float* Vs  = Ks + 64 * 65;
    float* Ps  = Vs + 64 * 65;
    float* m_s = Ps + 64 * 65;          // [64]
    float* l_s = m_s + 64;
    float* f_s = l_s + 64;

    int qt = blockIdx.x, h = blockIdx.y, b = blockIdx.z;
    const float* Qb = Q + (size_t)b * S_ * D_ + h * DH;
    const float* Vb = V + (size_t)b * S_ * D_ + h * DH;
    int tid = threadIdx.x;
    int tx = tid & 15, ty = tid >> 4;
    int r0 = ty * 4, c0 = tx * 4;

    for (int e = tid; e < 64 * 64; e += 256) {
        int r = e >> 6, c = e & 63;
        Qs[r * 65 + c] = Qb[(size_t)(qt * 64 + r) * D_ + c];
    }
    if (tid < 64) { m_s[tid] = -1e30f; l_s[tid] = 0.f; }
    float o[4][4];
#pragma unroll
    for (int i = 0; i < 4; i++)
#pragma unroll
        for (int j = 0; j < 4; j++) o[i][j] = 0.f;
    __syncthreads();

    for (int kt = 0; kt <= qt; kt++) {
        for (int e = tid; e < 64 * 64; e += 256) {
            int r = e >> 6, c = e & 63;
            Ks[r * 65 + c] = Qb[(size_t)(kt * 64 + r) * D_ + c];   // K == Q
            Vs[r * 65 + c] = Vb[(size_t)(kt * 64 + r) * D_ + c];
        }
        __syncthreads();

        float s[4][4];
#pragma unroll
        for (int i = 0; i < 4; i++)
#pragma unroll
            for (int j = 0; j < 4; j++) s[i][j] = 0.f;
#pragma unroll
        for (int kk = 0; kk < 64; kk++) {
            float qa[4], kb[4];
#pragma unroll
            for (int i = 0; i < 4; i++) qa[i] = Qs[(r0 + i) * 65 + kk];
#pragma unroll
            for (int j = 0; j < 4; j++) kb[j] = Ks[(c0 + j) * 65 + kk];
#pragma unroll
            for (int i = 0; i < 4; i++)
#pragma unroll
                for (int j = 0; j < 4; j++) s[i][j] += qa[i] * kb[j];
        }
        bool diag = (kt == qt);
#pragma unroll
        for (int i = 0; i < 4; i++)
#pragma unroll
            for (int j = 0; j < 4; j++) {
                float v = s[i][j] * 0.125f;           // 1/sqrt(64)
                if (diag && (c0 + j) > (r0 + i)) v = -1e30f;
                Ps[(r0 + i) * 65 + c0 + j] = v;
            }
        __syncthreads();

        if (tid < 64) {
            int r = tid;
            float* row = Ps + r * 65;
            float rm = -1e30f;
            for (int c = 0; c < 64; c++) rm = fmaxf(rm, row[c]);
            float mold = m_s[r];
            float mnew = fmaxf(mold, rm);
            float fac = __expf(mold - mnew);
            float rs = 0.f;
            for (int c = 0; c < 64; c++) {
                float p = __expf(row[c] - mnew);
                row[c] = p;
                rs += p;
            }
            l_s[r] = l_s[r] * fac + rs;
            m_s[r] = mnew;
            f_s[r] = fac;
        }
        __syncthreads();

#pragma unroll
        for (int i = 0; i < 4; i++) {
            float f = f_s[r0 + i];
#pragma unroll
            for (int j = 0; j < 4; j++) o[i][j] *= f;
        }
#pragma unroll
        for (int kk = 0; kk < 64; kk++) {
            float pa[4], vb[4];
#pragma unroll
            for (int i = 0; i < 4; i++) pa[i] = Ps[(r0 + i) * 65 + kk];
#pragma unroll
            for (int j = 0; j < 4; j++) vb[j] = Vs[kk * 65 + c0 + j];
#pragma unroll
            for (int i = 0; i < 4; i++)
#pragma unroll
                for (int j = 0; j < 4; j++) o[i][j] += pa[i] * vb[j];
        }
        __syncthreads();
    }

#pragma unroll
    for (int i = 0; i < 4; i++) {
        float inv = 1.f / l_s[r0 + i];
#pragma unroll
        for (int j = 0; j < 4; j++)
            O[(size_t)b * S_ * D_ + (size_t)(qt * 64 + r0 + i) * D_ + h * DH + c0 + j]
                = o[i][j] * inv;
    }
}

// ---------------- launch ----------------
extern "C" void kernel_launch(void* const* d_in, const int* in_sizes, int n_in,
                              void* d_out, int out_size)
{
    const float* x    = (const float*)d_in[0];
    const float* imp  = (const float*)d_in[1];
    const float* Wc   = (const float*)d_in[2];
    const float* Wqk  = (const float*)d_in[3];
    const float* Wv   = (const float*)d_in[4];
    const float* CN   = (const float*)d_in[5];
    const float* eQKw = (const float*)d_in[6];
    const float* eVw  = (const float*)d_in[7];
    const float* Wo   = (const float*)d_in[8];
    float* out = (float*)d_out;

    float *pSC, *ph, *peQK, *peV, *pQ, *pV, *pAO;
    cudaGetSymbolAddress((void**)&pSC,  g_SC);
    cudaGetSymbolAddress((void**)&ph,   g_h);
    cudaGetSymbolAddress((void**)&peQK, g_eQK);
    cudaGetSymbolAddress((void**)&peV,  g_eV);
    cudaGetSymbolAddress((void**)&pQ,   g_Q);
    cudaGetSymbolAddress((void**)&pV,   g_V);
    cudaGetSymbolAddress((void**)&pAO,  g_AO);

    zero_accum_kernel<<<4, 256>>>();
    routing_kernel<<<dim3(S_ / 32, B_), 512>>>(x, imp, Wc, Wqk, Wv);
    topk_kernel<<<1, 32>>>();

    mix_kernel<<<dim3(512, B_), 256>>>(CN,   pSC,  0, 8);
    mix_kernel<<<dim3(512, B_), 256>>>(eQKw, peQK, 8, 4);
    mix_kernel<<<dim3(512, B_), 256>>>(eVw,  peV, 12, 6);

    // h = X @ SC   (per batch: 1024x1024 @ 1024x128)
    sgemm_nn<<<dim3(128 / BN, 1024 / BM, B_), 256>>>(
        x, pSC, ph, 1024, 128, 1024, 1024, 128, 128,
        (long)S_ * D_, (long)D_ * R_, (long)S_ * R_);

    // Q = h @ eQK ; V = h @ eV   (per batch: 1024x128 @ 128x1024)
    sgemm_nn<<<dim3(1024 / BN, 1024 / BM, B_), 256>>>(
        ph, peQK, pQ, 1024, 1024, 128, 128, 1024, 1024,
        (long)S_ * R_, (long)R_ * D_, (long)S_ * D_);
    sgemm_nn<<<dim3(1024 / BN, 1024 / BM, B_), 256>>>(
        ph, peV, pV, 1024, 1024, 128, 128, 1024, 1024,
        (long)S_ * R_, (long)R_ * D_, (long)S_ * D_);

    // attention (K == Q)
    cudaFuncSetAttribute(attn_kernel, cudaFuncAttributeMaxDynamicSharedMemorySize,
                         ASM_F * sizeof(float));
    attn_kernel<<<dim3(S_ / 64, NH, B_), 256, ASM_F * sizeof(float)>>>(pQ, pV, pAO);

    // out = AO @ Wo^T  (8192x1024 @ 1024x1024^T)
    sgemm_bt<<<dim3(1024 / BN, 8192 / BM, 1), 256>>>(
        pAO, Wo, out, B_ * S_, 1024, 1024, 1024, 1024, 1024);
}

// round 2
// speedup vs baseline: 1.2919x; 1.2919x over previous
#include <cuda_runtime.h>
#include <math.h>

#define B_  8
#define S_  1024
#define D_  1024
#define R_  128
#define NH  16
#define DH  64

// ---------------- scratch (device globals; no allocation) ----------------
__device__ float g_accum[B_ * 128];
__device__ int   g_idx[B_ * 18];
__device__ float g_w[B_ * 18];
__device__ float g_SC [B_ * D_ * R_];          // [B,D,R]
__device__ float g_h  [B_ * S_ * R_];          // [B,S,R]
__device__ float g_eQK[B_ * R_ * D_];          // [B,R,D]
__device__ float g_eV [B_ * R_ * D_];
__device__ float g_Q  [B_ * S_ * D_];          // [B,S,D]
__device__ float g_V  [B_ * S_ * D_];
__device__ float g_AO [B_ * S_ * D_];          // attention output

// ---------------- zero accumulator ----------------
__global__ void zero_accum_kernel() {
    int i = blockIdx.x * 256 + threadIdx.x;
    if (i < B_ * 128) g_accum[i] = 0.f;
}

// ---------------- routing: logits + softmax + importance-weighted reduce ----------------
__global__ __launch_bounds__(512) void routing_kernel(
    const float* __restrict__ x, const float* __restrict__ importance,
    const float* __restrict__ Wc, const float* __restrict__ Wqk,
    const float* __restrict__ Wv)
{
    __shared__ float Xs[32][33];
    __shared__ float Ws[128][33];
    __shared__ float logits[32][130];
    __shared__ float ssum[32][3];
    __shared__ float simp[32];

    int b  = blockIdx.y;
    int t0 = blockIdx.x * 32;
    int tid = threadIdx.x;
    int o = tid & 127;
    int g = tid >> 7;

    float acc[8];
#pragma unroll
    for (int i = 0; i < 8; i++) acc[i] = 0.f;

    const float* xb = x + ((size_t)b * S_ + t0) * D_;

    for (int k0 = 0; k0 < D_; k0 += 32) {
        for (int e = tid; e < 32 * 32; e += 512) {
            int t = e >> 5, k = e & 31;
            Xs[t][k] = xb[t * D_ + k0 + k];
        }
        for (int e = tid; e < 128 * 32; e += 512) {
            int oo = e >> 5, k = e & 31;
            const float* wr = (oo < 64) ? Wc + oo * D_
                            : (oo < 96) ? Wqk + (oo - 64) * D_
                                        : Wv  + (oo - 96) * D_;
            Ws[oo][k] = wr[k0 + k];
        }
        __syncthreads();
#pragma unroll
        for (int kk = 0; kk < 32; kk++) {
            float w = Ws[o][kk];
#pragma unroll
            for (int i = 0; i < 8; i++) acc[i] += Xs[g * 8 + i][kk] * w;
        }
        __syncthreads();
    }
#pragma unroll
    for (int i = 0; i < 8; i++) logits[g * 8 + i][o] = acc[i];
    if (tid < 32) simp[tid] = importance[b * S_ + t0 + tid];
    __syncthreads();

    if (tid < 96) {
        int t = tid & 31;
        int seg = tid >> 5;
        int off = (seg == 0) ? 0 : (seg == 1) ? 64 : 96;
        int n   = (seg == 0) ? 64 : 32;
        float mx = -1e30f;
        for (int c = 0; c < n; c++) mx = fmaxf(mx, logits[t][off + c]);
        float sum = 0.f;
        for (int c = 0; c < n; c++) {
            float p = expf(logits[t][off + c] - mx);
            logits[t][off + c] = p;
            sum += p;
        }
        ssum[t][seg] = sum;
    }
    __syncthreads();

    if (tid < 128) {
        int seg = (tid < 64) ? 0 : (tid < 96) ? 1 : 2;
        float a = 0.f;
        for (int t = 0; t < 32; t++)
            a += simp[t] * logits[t][tid] / ssum[t][seg];
        atomicAdd(&g_accum[b * 128 + tid], a);
    }
}

// ---------------- exact top-k sparsify + renormalize ----------------
__global__ void topk_kernel() {
    int b = threadIdx.x;
    if (b >= B_) return;
    const int offs[3]  = {0, 64, 96};
    const int ns[3]    = {64, 32, 32};
    const int ks[3]    = {8, 4, 6};
    const int slots[3] = {0, 8, 12};
    for (int s = 0; s < 3; s++) {
        float vals[64];
        int n = ns[s], k = ks[s];
        for (int i = 0; i < n; i++) vals[i] = g_accum[b * 128 + offs[s] + i];
        float sum = 0.f;
        for (int j = 0; j < k; j++) {
            int am = 0; float mv = vals[0];
            for (int i = 1; i < n; i++) if (vals[i] > mv) { mv = vals[i]; am = i; }
            g_idx[b * 18 + slots[s] + j] = am;
            g_w  [b * 18 + slots[s] + j] = mv;
            sum += mv;
            vals[am] = -1e30f;
        }
        float inv = 1.f / (sum + 1e-8f);
        for (int j = 0; j < k; j++) g_w[b * 18 + slots[s] + j] *= inv;
    }
}

// ---------------- sparse neuron mix ----------------
__global__ void mix_kernel(const float* __restrict__ W, float* __restrict__ dst,
                           int slot, int cnt)
{
    int b = blockIdx.y;
    int e = blockIdx.x * 256 + threadIdx.x;
    float acc = 0.f;
    for (int j = 0; j < cnt; j++) {
        int   n = g_idx[b * 18 + slot + j];
        float w = g_w [b * 18 + slot + j];
        acc += w * W[(size_t)n * 131072 + e];
    }
    dst[(size_t)b * 131072 + e] = acc;
}

// ---------------- 64x64 SGEMM (for h, N=128) ----------------
#define BM 64
#define BN 64
#define BK 16
__global__ __launch_bounds__(256) void sgemm_nn(
    const float* __restrict__ A, const float* __restrict__ B, float* __restrict__ C,
    int M, int N, int K, int lda, int ldb, int ldc,
    long sA, long sB, long sC)
{
    __shared__ float As[BK][BM + 1];
    __shared__ float Bs[BK][BN + 1];
    A += (size_t)blockIdx.z * sA;
    B += (size_t)blockIdx.z * sB;
    C += (size_t)blockIdx.z * sC;
    int m0 = blockIdx.y * BM, n0 = blockIdx.x * BN;
    int tid = threadIdx.x;
    int tx = tid & 15, ty = tid >> 4;
    float acc[4][4];
#pragma unroll
    for (int i = 0; i < 4; i++)
#pragma unroll
        for (int j = 0; j < 4; j++) acc[i][j] = 0.f;

    for (int k0 = 0; k0 < K; k0 += BK) {
        for (int e = tid; e < BM * BK; e += 256) {
            int m = e >> 4, k = e & 15;
            As[k][m] = A[(size_t)(m0 + m) * lda + k0 + k];
        }
        for (int e = tid; e < BK * BN; e += 256) {
            int k = e >> 6, n = e & 63;
            Bs[k][n] = B[(size_t)(k0 + k) * ldb + n0 + n];
        }
        __syncthreads();
#pragma unroll
        for (int kk = 0; kk < BK; kk++) {
            float a[4], bb[4];
#pragma unroll
            for (int i = 0; i < 4; i++) a[i]  = As[kk][ty * 4 + i];
#pragma unroll
            for (int j = 0; j < 4; j++) bb[j] = Bs[kk][tx * 4 + j];
#pragma unroll
            for (int i = 0; i < 4; i++)
#pragma unroll
                for (int j = 0; j < 4; j++) acc[i][j] += a[i] * bb[j];
        }
        __syncthreads();
    }
#pragma unroll
    for (int i = 0; i < 4; i++)
#pragma unroll
        for (int j = 0; j < 4; j++)
            C[(size_t)(m0 + ty * 4 + i) * ldc + n0 + tx * 4 + j] = acc[i][j];
}

// ---------------- 128x128x16 SGEMM, 8x8 microtile (split-4 blocking) ----------------
// C = A(MxK,row) * B(KxN,row). 256 threads.
#define XP 132   // padded row length (528B, 16B aligned)
__global__ __launch_bounds__(256) void sgemm128_nn(
    const float* __restrict__ A, const float* __restrict__ B, float* __restrict__ C,
    int lda, int ldb, int ldc, long sA, long sB, long sC)
{
    __shared__ float As[16][XP];
    __shared__ float Bs[16][XP];
    A += (size_t)blockIdx.z * sA;
    B += (size_t)blockIdx.z * sB;
    C += (size_t)blockIdx.z * sC;
    int m0 = blockIdx.y * 128, n0 = blockIdx.x * 128;
    int tid = threadIdx.x;
    int tx = tid & 15, ty = tid >> 4;
    int ar = tid >> 1, ak = (tid & 1) * 8;   // A load: row, k-offset
    int bk = tid >> 4, bn = (tid & 15) * 8;  // B load: k-row, n-offset

    float acc[8][8];
#pragma unroll
    for (int i = 0; i < 8; i++)
#pragma unroll
        for (int j = 0; j < 8; j++) acc[i][j] = 0.f;

    const int K = (int)(sB / ldb) ? 0 : 0; (void)K; // (K passed via loop bound below)
    // K dimension: derive from caller via ldb? No — pass explicitly:
    // (we inline K as a parameter-free loop using lda? simpler: K passed in sA? )
    // -- K is passed through gridDim-independent constant below --
    for (int k0 = 0; k0 < lda; k0 += 16) {   // NOTE: only valid when K == lda (true for all call sites)
        float4 a0 = *(const float4*)&A[(size_t)(m0 + ar) * lda + k0 + ak];
        float4 a1 = *(const float4*)&A[(size_t)(m0 + ar) * lda + k0 + ak + 4];
        As[ak + 0][ar] = a0.x; As[ak + 1][ar] = a0.y;
        As[ak + 2][ar] = a0.z; As[ak + 3][ar] = a0.w;
        As[ak + 4][ar] = a1.x; As[ak + 5][ar] = a1.y;
        As[ak + 6][ar] = a1.z; As[ak + 7][ar] = a1.w;
        float4 b0 = *(const float4*)&B[(size_t)(k0 + bk) * ldb + n0 + bn];
        float4 b1 = *(const float4*)&B[(size_t)(k0 + bk) * ldb + n0 + bn + 4];
        *(float4*)&Bs[bk][bn]     = b0;
        *(float4*)&Bs[bk][bn + 4] = b1;
        __syncthreads();
#pragma unroll
        for (int kk = 0; kk < 16; kk++) {
            float a[8], bv[8];
            float4 t;
            t = *(const float4*)&As[kk][ty * 4];      a[0]=t.x; a[1]=t.y; a[2]=t.z; a[3]=t.w;
            t = *(const float4*)&As[kk][64 + ty * 4]; a[4]=t.x; a[5]=t.y; a[6]=t.z; a[7]=t.w;
            t = *(const float4*)&Bs[kk][tx * 4];      bv[0]=t.x; bv[1]=t.y; bv[2]=t.z; bv[3]=t.w;
            t = *(const float4*)&Bs[kk][64 + tx * 4]; bv[4]=t.x; bv[5]=t.y; bv[6]=t.z; bv[7]=t.w;
#pragma unroll
            for (int i = 0; i < 8; i++)
#pragma unroll
                for (int j = 0; j < 8; j++) acc[i][j] += a[i] * bv[j];
        }
        __syncthreads();
    }
#pragma unroll
    for (int i = 0; i < 8; i++) {
        int ri = (i < 4) ? ty * 4 + i : 64 + ty * 4 + (i - 4);
        float4 lo = make_float4(acc[i][0], acc[i][1], acc[i][2], acc[i][3]);
        float4 hi = make_float4(acc[i][4], acc[i][5], acc[i][6], acc[i][7]);
        *(float4*)&C[(size_t)(m0 + ri) * ldc + n0 + tx * 4]      = lo;
        *(float4*)&C[(size_t)(m0 + ri) * ldc + n0 + 64 + tx * 4] = hi;
    }
}

// ---------------- 128x128x16 SGEMM, B transposed: C = A * Bt^T ----------------
__global__ __launch_bounds__(256) void sgemm128_bt(
    const float* __restrict__ A, const float* __restrict__ Bt, float* __restrict__ C,
    int K, int lda, int ldb, int ldc)
{
    __shared__ float As[16][XP];
    __shared__ float Bs[16][XP];
    int m0 = blockIdx.y * 128, n0 = blockIdx.x * 128;
    int tid = threadIdx.x;
    int tx = tid & 15, ty = tid >> 4;
    int ar = tid >> 1, ak = (tid & 1) * 8;

    float acc[8][8];
#pragma unroll
    for (int i = 0; i < 8; i++)
#pragma unroll
        for (int j = 0; j < 8; j++) acc[i][j] = 0.f;

    for (int k0 = 0; k0 < K; k0 += 16) {
        float4 a0 = *(const float4*)&A[(size_t)(m0 + ar) * lda + k0 + ak];
        float4 a1 = *(const float4*)&A[(size_t)(m0 + ar) * lda + k0 + ak + 4];
        As[ak + 0][ar] = a0.x; As[ak + 1][ar] = a0.y;
        As[ak + 2][ar] = a0.z; As[ak + 3][ar] = a0.w;
        As[ak + 4][ar] = a1.x; As[ak + 5][ar] = a1.y;
        As[ak + 6][ar] = a1.z; As[ak + 7][ar] = a1.w;
        float4 b0 = *(const float4*)&Bt[(size_t)(n0 + ar) * ldb + k0 + ak];
        float4 b1 = *(const float4*)&Bt[(size_t)(n0 + ar) * ldb + k0 + ak + 4];
        Bs[ak + 0][ar] = b0.x; Bs[ak + 1][ar] = b0.y;
        Bs[ak + 2][ar] = b0.z; Bs[ak + 3][ar] = b0.w;
        Bs[ak + 4][ar] = b1.x; Bs[ak + 5][ar] = b1.y;
        Bs[ak + 6][ar] = b1.z; Bs[ak + 7][ar] = b1.w;
        __syncthreads();
#pragma unroll
        for (int kk = 0; kk < 16; kk++) {
            float a[8], bv[8];
            float4 t;
            t = *(const float4*)&As[kk][ty * 4];      a[0]=t.x; a[1]=t.y; a[2]=t.z; a[3]=t.w;
            t = *(const float4*)&As[kk][64 + ty * 4]; a[4]=t.x; a[5]=t.y; a[6]=t.z; a[7]=t.w;
            t = *(const float4*)&Bs[kk][tx * 4];      bv[0]=t.x; bv[1]=t.y; bv[2]=t.z; bv[3]=t.w;
            t = *(const float4*)&Bs[kk][64 + tx * 4]; bv[4]=t.x; bv[5]=t.y; bv[6]=t.z; bv[7]=t.w;
#pragma unroll
            for (int i = 0; i < 8; i++)
#pragma unroll
                for (int j = 0; j < 8; j++) acc[i][j] += a[i] * bv[j];
        }
        __syncthreads();
    }
#pragma unroll
    for (int i = 0; i < 8; i++) {
        int ri = (i < 4) ? ty * 4 + i : 64 + ty * 4 + (i - 4);
        float4 lo = make_float4(acc[i][0], acc[i][1], acc[i][2], acc[i][3]);
        float4 hi = make_float4(acc[i][4], acc[i][5], acc[i][6], acc[i][7]);
        *(float4*)&C[(size_t)(m0 + ri) * ldc + n0 + tx * 4]      = lo;
        *(float4*)&C[(size_t)(m0 + ri) * ldc + n0 + 64 + tx * 4] = hi;
    }
}

// ---------------- flash attention, fp32, K == Q, causal ----------------
// Br=128, Bc=64. 256 threads, 8x4 microtile. Q/K stored dh-major in smem.
// smem floats: Qts 64*132 + Kts 64*68 + Vs 64*68 + Ps 128*68 + 3*128
#define ATT_SMEM_F (64*132 + 64*68 + 64*68 + 128*68 + 384)
__global__ __launch_bounds__(256) void attn_kernel(
    const float* __restrict__ Q, const float* __restrict__ V, float* __restrict__ O)
{
    extern __shared__ float sm[];
    float* Qts = sm;                   // [64][132]  (dh, qrow)
    float* Kts = Qts + 64 * 132;       // [64][68]   (dh, krow)
    float* Vs  = Kts + 64 * 68;        // [64][68]   (krow, dh)
    float* Ps  = Vs  + 64 * 68;        // [128][68]
    float* m_s = Ps  + 128 * 68;
    float* l_s = m_s + 128;
    float* f_s = l_s + 128;

    int qt = blockIdx.x, h = blockIdx.y, b = blockIdx.z;
    const float* Qb = Q + (size_t)b * S_ * D_ + h * DH;
    const float* Vb = V + (size_t)b * S_ * D_ + h * DH;
    int tid = threadIdx.x;
    int tx = tid & 15, ty = tid >> 4;
    int c0 = tx * 4;
    int ri[8];
#pragma unroll
    for (int i = 0; i < 8; i++) ri[i] = (i < 4) ? ty * 4 + i : 64 + ty * 4 + (i - 4);

    // load Q tile transposed (once)
    for (int e = tid; e < 128 * 64; e += 256) {
        int r = e >> 6, c = e & 63;
        Qts[c * 132 + r] = Qb[(size_t)(qt * 128 + r) * D_ + c];
    }
    if (tid < 128) { m_s[tid] = -1e30f; l_s[tid] = 0.f; }
    float o[8][4];
#pragma unroll
    for (int i = 0; i < 8; i++)
#pragma unroll
        for (int j = 0; j < 4; j++) o[i][j] = 0.f;
    __syncthreads();

    int ntiles = 2 * qt + 2;
    for (int kt = 0; kt < ntiles; kt++) {
        for (int e = tid; e < 64 * 64; e += 256) {
            int r = e >> 6, c = e & 63;
            float kv = Qb[(size_t)(kt * 64 + r) * D_ + c];   // K == Q
            Kts[c * 68 + r] = kv;
            Vs[r * 68 + c]  = Vb[(size_t)(kt * 64 + r) * D_ + c];
        }
        __syncthreads();

        float s[8][4];
#pragma unroll
        for (int i = 0; i < 8; i++)
#pragma unroll
            for (int j = 0; j < 4; j++) s[i][j] = 0.f;
#pragma unroll 4
        for (int kk = 0; kk < 64; kk++) {
            float qa[8], kb[4];
            float4 t;
            t = *(const float4*)&Qts[kk * 132 + ty * 4];
            qa[0]=t.x; qa[1]=t.y; qa[2]=t.z; qa[3]=t.w;
            t = *(const float4*)&Qts[kk * 132 + 64 + ty * 4];
            qa[4]=t.x; qa[5]=t.y; qa[6]=t.z; qa[7]=t.w;
            t = *(const float4*)&Kts[kk * 68 + c0];
            kb[0]=t.x; kb[1]=t.y; kb[2]=t.z; kb[3]=t.w;
#pragma unroll
            for (int i = 0; i < 8; i++)
#pragma unroll
                for (int j = 0; j < 4; j++) s[i][j] += qa[i] * kb[j];
        }
        bool maskt = (kt >= 2 * qt);
#pragma unroll
        for (int i = 0; i < 8; i++) {
            int grow = qt * 128 + ri[i];
#pragma unroll
            for (int j = 0; j < 4; j++) {
                float v = s[i][j] * 0.125f;
                if (maskt && (kt * 64 + c0 + j) > grow) v = -1e30f;
                Ps[ri[i] * 68 + c0 + j] = v;
            }
        }
        __syncthreads();

        // online softmax: 2 threads per row
        {
            int r = tid >> 1, hh = tid & 1;
            float* row = Ps + r * 68 + hh * 32;
            float pm = -1e30f;
#pragma unroll 8
            for (int c = 0; c < 32; c++) pm = fmaxf(pm, row[c]);
            pm = fmaxf(pm, __shfl_xor_sync(0xffffffffu, pm, 1));
            float mold = m_s[r];
            float mnew = fmaxf(mold, pm);
            float ps = 0.f;
#pragma unroll 8
            for (int c = 0; c < 32; c++) {
                float p = __expf(row[c] - mnew);
                row[c] = p;
                ps += p;
            }
            ps += __shfl_xor_sync(0xffffffffu, ps, 1);
            if (hh == 0) {
                float fac = __expf(mold - mnew);
                f_s[r] = fac;
                l_s[r] = l_s[r] * fac + ps;
                m_s[r] = mnew;
            }
        }
        __syncthreads();

#pragma unroll
        for (int i = 0; i < 8; i++) {
            float f = f_s[ri[i]];
#pragma unroll
            for (int j = 0; j < 4; j++) o[i][j] *= f;
        }
#pragma unroll 4
        for (int kk = 0; kk < 64; kk++) {
            float pa[8], vb[4];
#pragma unroll
            for (int i = 0; i < 8; i++) pa[i] = Ps[ri[i] * 68 + kk];
            float4 t = *(const float4*)&Vs[kk * 68 + c0];
            vb[0]=t.x; vb[1]=t.y; vb[2]=t.z; vb[3]=t.w;
#pragma unroll
            for (int i = 0; i < 8; i++)
#pragma unroll
                for (int j = 0; j < 4; j++) o[i][j] += pa[i] * vb[j];
        }
        __syncthreads();
    }

#pragma unroll
    for (int i = 0; i < 8; i++) {
        float inv = 1.f / l_s[ri[i]];
        float4 v = make_float4(o[i][0] * inv, o[i][1] * inv, o[i][2] * inv, o[i][3] * inv);
        *(float4*)&O[(size_t)b * S_ * D_ + (size_t)(qt * 128 + ri[i]) * D_ + h * DH + c0] = v;
    }
}

// ---------------- launch ----------------
extern "C" void kernel_launch(void* const* d_in, const int* in_sizes, int n_in,
                              void* d_out, int out_size)
{
    const float* x    = (const float*)d_in[0];
    const float* imp  = (const float*)d_in[1];
    const float* Wc   = (const float*)d_in[2];
    const float* Wqk  = (const float*)d_in[3];
    const float* Wv   = (const float*)d_in[4];
    const float* CN   = (const float*)d_in[5];
    const float* eQKw = (const float*)d_in[6];
    const float* eVw  = (const float*)d_in[7];
    const float* Wo   = (const float*)d_in[8];
    float* out = (float*)d_out;

    float *pSC, *ph, *peQK, *peV, *pQ, *pV, *pAO;
    cudaGetSymbolAddress((void**)&pSC,  g_SC);
    cudaGetSymbolAddress((void**)&ph,   g_h);
    cudaGetSymbolAddress((void**)&peQK, g_eQK);
    cudaGetSymbolAddress((void**)&peV,  g_eV);
    cudaGetSymbolAddress((void**)&pQ,   g_Q);
    cudaGetSymbolAddress((void**)&pV,   g_V);
    cudaGetSymbolAddress((void**)&pAO,  g_AO);

    zero_accum_kernel<<<4, 256>>>();
    routing_kernel<<<dim3(S_ / 32, B_), 512>>>(x, imp, Wc, Wqk, Wv);
    topk_kernel<<<1, 32>>>();

    mix_kernel<<<dim3(512, B_), 256>>>(CN,   pSC,  0, 8);
    mix_kernel<<<dim3(512, B_), 256>>>(eQKw, peQK, 8, 4);
    mix_kernel<<<dim3(512, B_), 256>>>(eVw,  peV, 12, 6);

    // h = X @ SC   (per batch: 1024x128, K=1024) — 64x64 tiles for occupancy
    sgemm_nn<<<dim3(128 / BN, 1024 / BM, B_), 256>>>(
        x, pSC, ph, 1024, 128, 1024, 1024, 128, 128,
        (long)S_ * D_, (long)D_ * R_, (long)S_ * R_);

    // Q = h @ eQK ; V = h @ eV   (per batch: 1024x1024, K=128=lda of h)
    sgemm128_nn<<<dim3(8, 8, B_), 256>>>(
        ph, peQK, pQ, 128, 1024, 1024,
        (long)S_ * R_, (long)R_ * D_, (long)S_ * D_);
    sgemm128_nn<<<dim3(8, 8, B_), 256>>>(
        ph, peV, pV, 128, 1024, 1024,
        (long)S_ * R_, (long)R_ * D_, (long)S_ * D_);

    // attention (K == Q), Br=128
    cudaFuncSetAttribute(attn_kernel, cudaFuncAttributeMaxDynamicSharedMemorySize,
                         ATT_SMEM_F * sizeof(float));
    attn_kernel<<<dim3(S_ / 128, NH, B_), 256, ATT_SMEM_F * sizeof(float)>>>(pQ, pV, pAO);

    // out = AO @ Wo^T  (8192x1024, K=1024)
    sgemm128_bt<<<dim3(8, 64, 1), 256>>>(pAO, Wo, out, 1024, 1024, 1024, 1024);
}